// round 5
// baseline (speedup 1.0000x reference)
#include <cuda_runtime.h>
#include <cuda_bf16.h>
#include <math.h>
#include <stdint.h>

#define NROWS 65536
#define D 256
#define K 1024
#define QSIZE (NROWS*D)
#define TAU2 2.5e-4f

// ---------------- scratch ----------------
__device__ __align__(128) float g_eT[K*D];
__device__ __align__(128) float g_en2[K];
__device__ __align__(128) float g_zn2[NROWS];
__device__ int   g_idx[NROWS];
__device__ float g_part[8192];
__device__ int   g_hist[K];
__device__ __align__(128) __nv_bfloat16 g_ebh[K*D];
__device__ __align__(128) __nv_bfloat16 g_ebl[K*D];
__device__ int   g_flag[NROWS];
__device__ int   g_nflag;
__device__ int   g_bad;
__device__ __align__(128) float g_dist[(size_t)NROWS*K];   // raw approx distances

// ---------------- asm helpers ----------------
__device__ __forceinline__ uint32_t smem_u32(const void* p) {
    uint32_t a;
    asm("{ .reg .u64 t; cvta.to.shared.u64 t, %1; cvt.u32.u64 %0, t; }" : "=r"(a) : "l"(p));
    return a;
}
__device__ __forceinline__ void ldsm4(uint32_t* r, uint32_t addr) {
    asm volatile("ldmatrix.sync.aligned.m8n8.x4.shared.b16 {%0,%1,%2,%3}, [%4];"
        : "=r"(r[0]), "=r"(r[1]), "=r"(r[2]), "=r"(r[3]) : "r"(addr));
}
__device__ __forceinline__ void mma16816(float* c, const uint32_t* a, uint32_t b0, uint32_t b1) {
    asm volatile("mma.sync.aligned.m16n8k16.row.col.f32.bf16.bf16.f32 "
        "{%0,%1,%2,%3}, {%4,%5,%6,%7}, {%8,%9}, {%0,%1,%2,%3};"
        : "+f"(c[0]), "+f"(c[1]), "+f"(c[2]), "+f"(c[3])
        : "r"(a[0]), "r"(a[1]), "r"(a[2]), "r"(a[3]), "r"(b0), "r"(b1));
}
__device__ __forceinline__ void cp16(uint32_t dst, const void* src) {
    asm volatile("cp.async.cg.shared.global [%0], [%1], 16;" :: "r"(dst), "l"(src) : "memory");
}
#define CP_COMMIT() asm volatile("cp.async.commit_group;" ::: "memory")
#define CP_WAIT1()  asm volatile("cp.async.wait_group 1;" ::: "memory")
#define CP_WAIT0()  asm volatile("cp.async.wait_group 0;" ::: "memory")

// ---------------- small kernels ----------------
__global__ void k_init() {
    int t = blockIdx.x * blockDim.x + threadIdx.x;
    if (t < K) g_hist[t] = 0;
    if (t == 0) { g_nflag = 0; g_bad = 0; }
}

__global__ void k_en2(const float* __restrict__ e) {
    int k = blockIdx.x * blockDim.x + threadIdx.x;
    if (k >= K) return;
    float s = 0.f;
    for (int d = 0; d < D; ++d) {
        float v = e[d * K + k];
        s = __fadd_rn(s, __fmul_rn(v, v));
    }
    g_en2[k] = s;
}

__global__ void k_prep(const float* __restrict__ e) {
    __shared__ float t[32][33];
    int kb = blockIdx.x * 32, db = blockIdx.y * 32;
    int tx = threadIdx.x, ty = threadIdx.y;
    #pragma unroll
    for (int i = 0; i < 32; i += 8)
        t[ty + i][tx] = e[(db + ty + i) * K + kb + tx];
    __syncthreads();
    #pragma unroll
    for (int i = 0; i < 32; i += 8) {
        float v = t[tx][ty + i];
        int off = (kb + ty + i) * D + db + tx;
        g_eT[off] = v;
        __nv_bfloat16 hb = __float2bfloat16_rn(v);
        g_ebh[off] = hb;
        g_ebl[off] = __float2bfloat16_rn(v - __bfloat162float(hb));
    }
}

__global__ void k_zn2(const float* __restrict__ z) {
    __shared__ float sz[32][257];
    int row0 = blockIdx.x * 32;
    int tid = threadIdx.x;
    #pragma unroll
    for (int i = 0; i < 32; i++) {
        int l = i * 256 + tid;
        int r = l >> 8, d = l & 255;
        sz[r][d] = z[(size_t)(row0 + r) * D + d];
    }
    __syncthreads();
    if (tid < 32) {
        float s = 0.f;
        for (int d = 0; d < D; ++d) {
            float v = sz[tid][d];
            s = __fadd_rn(s, __fmul_rn(v, v));
        }
        g_zn2[row0 + tid] = s;
    }
}

// ---------------- Phase A: bf16x3 HMMA GEMM, writes raw distances ----------------
#define PITCH 528
#define SA_LO 67584
#define SB_OFF 135168
#define SB_BUF 33792
#define SB_HL  16896
#define SEN2   202752
#define SMEM_TOT 203008

__device__ __forceinline__ void stageB(char* smem, uint32_t sb, int chunk, int buf, int tid) {
    #pragma unroll
    for (int i = 0; i < 8; i++) {
        int lin = i * 256 + tid;
        int hl = lin >> 10, rem = lin & 1023, r = rem >> 5, s = rem & 31;
        const __nv_bfloat16* src = (hl ? g_ebl : g_ebh)
            + ((size_t)(chunk * 32 + r) << 8) + (s << 3);
        uint32_t dst = sb + SB_OFF + buf * SB_BUF + hl * SB_HL + r * PITCH + (s << 4);
        cp16(dst, src);
    }
    if (tid < 32)
        *(float*)(smem + SEN2 + buf * 128 + tid * 4) = g_en2[chunk * 32 + tid];
}

__global__ __launch_bounds__(256, 1)
void k_phaseA(const float* __restrict__ z) {
    extern __shared__ char smem[];
    uint32_t sb = smem_u32(smem);
    int tid = threadIdx.x, lane = tid & 31, wid = tid >> 5;
    int warp_m = wid >> 1, warp_n = wid & 1;
    int row0 = blockIdx.x * 128;

    #pragma unroll 4
    for (int i = 0; i < 32; i++) {
        int gi = i * 256 + tid;
        int r = gi >> 6, c4 = (gi & 63) << 2;
        const float4 v = *(const float4*)(z + ((size_t)(row0 + r) << 8) + c4);
        __nv_bfloat16 h0 = __float2bfloat16_rn(v.x), h1 = __float2bfloat16_rn(v.y);
        __nv_bfloat16 h2 = __float2bfloat16_rn(v.z), h3 = __float2bfloat16_rn(v.w);
        __nv_bfloat16 l0 = __float2bfloat16_rn(v.x - __bfloat162float(h0));
        __nv_bfloat16 l1 = __float2bfloat16_rn(v.y - __bfloat162float(h1));
        __nv_bfloat16 l2 = __float2bfloat16_rn(v.z - __bfloat162float(h2));
        __nv_bfloat16 l3 = __float2bfloat16_rn(v.w - __bfloat162float(h3));
        uint2 hw, lw;
        hw.x = (uint32_t)__bfloat16_as_ushort(h0) | ((uint32_t)__bfloat16_as_ushort(h1) << 16);
        hw.y = (uint32_t)__bfloat16_as_ushort(h2) | ((uint32_t)__bfloat16_as_ushort(h3) << 16);
        lw.x = (uint32_t)__bfloat16_as_ushort(l0) | ((uint32_t)__bfloat16_as_ushort(l1) << 16);
        lw.y = (uint32_t)__bfloat16_as_ushort(l2) | ((uint32_t)__bfloat16_as_ushort(l3) << 16);
        int off = r * PITCH + (c4 << 1);
        *(uint2*)(smem + off) = hw;
        *(uint2*)(smem + SA_LO + off) = lw;
    }
    stageB(smem, sb, 0, 0, tid);
    CP_COMMIT();

    uint32_t a_off = sb + (uint32_t)(warp_m * 32 + (lane & 15)) * PITCH + ((lane >> 4) << 4);
    uint32_t b_off = sb + SB_OFF
        + (uint32_t)(warp_n * 16 + (lane & 7) + ((lane >> 4) << 3)) * PITCH
        + (((lane >> 3) & 1) << 4);

    for (int ch = 0; ch < 32; ch++) {
        int buf = ch & 1;
        if (ch + 1 < 32) { stageB(smem, sb, ch + 1, buf ^ 1, tid); CP_COMMIT(); CP_WAIT1(); }
        else CP_WAIT0();
        __syncthreads();

        float acc[2][2][4];
        #pragma unroll
        for (int mt = 0; mt < 2; mt++)
            #pragma unroll
            for (int nt = 0; nt < 2; nt++)
                #pragma unroll
                for (int q = 0; q < 4; q++) acc[mt][nt][q] = 0.f;

        #pragma unroll
        for (int seg = 0; seg < 3; seg++) {
            uint32_t ab = a_off + (seg == 2 ? SA_LO : 0);
            uint32_t bb = b_off + buf * SB_BUF + (seg == 1 ? SB_HL : 0);
            #pragma unroll
            for (int kk = 0; kk < 16; kk++) {
                uint32_t A0[4], A1[4], B[4];
                ldsm4(A0, ab + kk * 32);
                ldsm4(A1, ab + kk * 32 + 16 * PITCH);
                ldsm4(B, bb + kk * 32);
                mma16816(acc[0][0], A0, B[0], B[1]);
                mma16816(acc[0][1], A0, B[2], B[3]);
                mma16816(acc[1][0], A1, B[0], B[1]);
                mma16816(acc[1][1], A1, B[2], B[3]);
            }
        }

        // epilogue: write raw distances (zn2 omitted — constant per row)
        const float* en2s = (const float*)(smem + SEN2 + buf * 128);
        #pragma unroll
        for (int mt = 0; mt < 2; mt++) {
            #pragma unroll
            for (int nt = 0; nt < 2; nt++) {
                int cb = warp_n * 16 + nt * 8 + (lane & 3) * 2;
                float e0 = en2s[cb], e1 = en2s[cb + 1];
                int col = ch * 32 + cb;
                #pragma unroll
                for (int half = 0; half < 2; half++) {
                    int row = row0 + warp_m * 32 + mt * 16 + half * 8 + (lane >> 2);
                    float2 dp;
                    dp.x = __fsub_rn(e0, 2.0f * acc[mt][nt][half * 2]);
                    dp.y = __fsub_rn(e1, 2.0f * acc[mt][nt][half * 2 + 1]);
                    *(float2*)&g_dist[((size_t)row << 10) + col] = dp;
                }
            }
        }
        __syncthreads();
    }
}

// ---------------- reduce: argmin + margin over g_dist (simple, verifiable) ----------------
__global__ void k_reduce() {
    int warp = threadIdx.x >> 5, lane = threadIdx.x & 31;
    int row = blockIdx.x * 8 + warp;
    const float* dr = g_dist + ((size_t)row << 10);
    float v[32];
    float b1 = INFINITY; int i1 = 0;
    #pragma unroll
    for (int j = 0; j < 32; j++) {
        v[j] = dr[j * 32 + lane];
        int code = j * 32 + lane;
        if (v[j] < b1) { b1 = v[j]; i1 = code; }
    }
    #pragma unroll
    for (int off = 16; off; off >>= 1) {
        float ov = __shfl_xor_sync(0xffffffffu, b1, off);
        int oi = __shfl_xor_sync(0xffffffffu, i1, off);
        if (ov < b1 || (ov == b1 && oi < i1)) { b1 = ov; i1 = oi; }
    }
    // pass 2: min excluding the winning index
    float s = INFINITY;
    #pragma unroll
    for (int j = 0; j < 32; j++) {
        int code = j * 32 + lane;
        if (code != i1) s = fminf(s, v[j]);
    }
    #pragma unroll
    for (int off = 16; off; off >>= 1)
        s = fminf(s, __shfl_xor_sync(0xffffffffu, s, off));
    if (lane == 0) {
        g_idx[row] = i1;
        if (s - b1 < TAU2) {
            int p = atomicAdd(&g_nflag, 1);
            g_flag[p] = row;
        }
    }
}

// ---------------- block-batched exact rescue (reference arithmetic) ----------------
#define RSP 260
#define RS_SMEM ((32*RSP + 64*RSP + 256 + 256) * 4)

__global__ __launch_bounds__(256, 1)
void k_rescue(const float* __restrict__ z) {
    extern __shared__ float rs[];
    float* sz = rs;                      // [32][260]
    float* se = rs + 32 * RSP;           // [64][260]
    float* mbv = se + 64 * RSP;          // [256]
    int*   mbi = (int*)(mbv + 256);      // [256]
    int tid = threadIdx.x;
    int r = tid >> 3, cs = tid & 7;
    int n = g_nflag;

    for (int base = blockIdx.x * 32; base < n; base += gridDim.x * 32) {
        int cnt = min(32, n - base);
        for (int i = tid; i < cnt * 64; i += 256) {
            int rr = i >> 6, q = (i & 63) << 2;
            int row = g_flag[base + rr];
            float4 vv = *(const float4*)&z[((size_t)row << 8) + q];
            sz[rr * RSP + q] = vv.x; sz[rr * RSP + q + 1] = vv.y;
            sz[rr * RSP + q + 2] = vv.z; sz[rr * RSP + q + 3] = vv.w;
        }
        float myzn2 = (r < cnt) ? g_zn2[g_flag[base + r]] : 0.f;
        float bv = INFINITY; int bi = 0;
        for (int cc = 0; cc < 16; cc++) {
            __syncthreads();
            for (int i = tid; i < 64 * 64; i += 256) {
                int c = i >> 6, q = (i & 63) << 2;
                float4 vv = *(const float4*)&g_eT[((size_t)(cc * 64 + c) << 8) + q];
                se[c * RSP + q] = vv.x; se[c * RSP + q + 1] = vv.y;
                se[c * RSP + q + 2] = vv.z; se[c * RSP + q + 3] = vv.w;
            }
            __syncthreads();
            if (r < cnt) {
                #pragma unroll
                for (int m = 0; m < 8; m++) {
                    int c = cs + 8 * m;
                    float t = 0.f;
                    #pragma unroll 8
                    for (int d = 0; d < 256; d++)
                        t = fmaf(sz[r * RSP + d], se[c * RSP + d], t);
                    int code = cc * 64 + c;
                    float dist = __fsub_rn(__fadd_rn(myzn2, g_en2[code]), 2.0f * t);
                    if (dist < bv) { bv = dist; bi = code; }
                }
            }
        }
        mbv[tid] = bv; mbi[tid] = bi;
        __syncthreads();
        if (tid < cnt) {
            float fb = mbv[tid * 8]; int fi = mbi[tid * 8];
            #pragma unroll
            for (int s2 = 1; s2 < 8; s2++) {
                float vv = mbv[tid * 8 + s2]; int ii = mbi[tid * 8 + s2];
                if (vv < fb || (vv == fb && ii < fi)) { fb = vv; fi = ii; }
            }
            g_idx[g_flag[base + tid]] = fi;
        }
        __syncthreads();
    }
}

// ---------------- sampled exact checker (256 rows) ----------------
__global__ void k_check(const float* __restrict__ z, const float* __restrict__ e) {
    __shared__ float srow[8][256];
    int warp = threadIdx.x >> 5, lane = threadIdx.x & 31;
    int row = (blockIdx.x * 8 + warp) * 256 + 128;
    for (int d = lane; d < 256; d += 32) srow[warp][d] = z[((size_t)row << 8) + d];
    __syncwarp();
    float zn2 = g_zn2[row];
    float bv = INFINITY; int bi = 0;
    for (int c = 0; c < 32; c++) {
        int code = c * 32 + lane;
        float t = 0.f;
        #pragma unroll 8
        for (int d = 0; d < 256; d++)
            t = fmaf(srow[warp][d], e[d * K + code], t);
        float dist = __fsub_rn(__fadd_rn(zn2, g_en2[code]), 2.0f * t);
        if (dist < bv) { bv = dist; bi = code; }
    }
    #pragma unroll
    for (int off = 16; off; off >>= 1) {
        float ov = __shfl_xor_sync(0xffffffffu, bv, off);
        int oi = __shfl_xor_sync(0xffffffffu, bi, off);
        if (ov < bv || (ov == bv && oi < bi)) { bv = ov; bi = oi; }
    }
    if (lane == 0) {
        int mine = g_idx[row];
        if (mine != bi) {
            float t = 0.f;
            for (int d = 0; d < 256; d++)
                t = fmaf(srow[warp][d], e[d * K + mine], t);
            float dm = __fsub_rn(__fadd_rn(zn2, g_en2[mine]), 2.0f * t);
            if (dm > bv + 1e-5f) atomicAdd(&g_bad, 1);
        }
    }
}

// ---------------- conditional full fp32 fallback (R1 argmin) ----------------
#define BM 128
#define BN 128
#define BK 16
#define TM 8
#define TN 8
#define BMP 132

__global__ __launch_bounds__(256, 2)
void k_fallback(const float* __restrict__ z, const float* __restrict__ e) {
    if (g_bad == 0) return;
    __shared__ float s_zT[BK][BMP];
    __shared__ float s_e[BK][BN];
    __shared__ float s_en2[BN];
    __shared__ float m_v[BM][16];
    __shared__ int   m_i[BM][16];

    int tid = threadIdx.x;
    int tx = tid & 15, ty = tid >> 4;
    int row0 = blockIdx.x * BM;

    float bestv[TM]; int besti[TM]; float my_zn2[TM];
    #pragma unroll
    for (int i = 0; i < TM; i++) {
        bestv[i] = INFINITY; besti[i] = 0;
        my_zn2[i] = g_zn2[row0 + ty * TM + i];
    }

    for (int kc = 0; kc < K; kc += BN) {
        __syncthreads();
        if (tid < BN) s_en2[tid] = g_en2[kc + tid];
        float acc[TM][TN];
        #pragma unroll
        for (int i = 0; i < TM; i++)
            #pragma unroll
            for (int j = 0; j < TN; j++) acc[i][j] = 0.f;
        for (int dk = 0; dk < D; dk += BK) {
            #pragma unroll
            for (int i = 0; i < 8; i++) {
                int l = i * 256 + tid;
                int r = l >> 4, d = l & 15;
                s_zT[d][r] = z[(size_t)(row0 + r) * D + dk + d];
                int d2 = l >> 7, k2 = l & 127;
                s_e[d2][k2] = e[(dk + d2) * K + kc + k2];
            }
            __syncthreads();
            #pragma unroll
            for (int d = 0; d < BK; d++) {
                float a[TM], b[TN];
                float4 a0 = *(const float4*)&s_zT[d][ty * TM];
                float4 a1 = *(const float4*)&s_zT[d][ty * TM + 4];
                float4 b0 = *(const float4*)&s_e[d][tx * TN];
                float4 b1 = *(const float4*)&s_e[d][tx * TN + 4];
                a[0]=a0.x; a[1]=a0.y; a[2]=a0.z; a[3]=a0.w;
                a[4]=a1.x; a[5]=a1.y; a[6]=a1.z; a[7]=a1.w;
                b[0]=b0.x; b[1]=b0.y; b[2]=b0.z; b[3]=b0.w;
                b[4]=b1.x; b[5]=b1.y; b[6]=b1.z; b[7]=b1.w;
                #pragma unroll
                for (int i = 0; i < TM; i++)
                    #pragma unroll
                    for (int j = 0; j < TN; j++)
                        acc[i][j] = fmaf(a[i], b[j], acc[i][j]);
            }
            __syncthreads();
        }
        #pragma unroll
        for (int i = 0; i < TM; i++) {
            #pragma unroll
            for (int j = 0; j < TN; j++) {
                float dist = __fsub_rn(__fadd_rn(my_zn2[i], s_en2[tx * TN + j]),
                                       2.0f * acc[i][j]);
                int code = kc + tx * TN + j;
                if (dist < bestv[i]) { bestv[i] = dist; besti[i] = code; }
            }
        }
    }
    __syncthreads();
    #pragma unroll
    for (int i = 0; i < TM; i++) {
        m_v[ty * TM + i][tx] = bestv[i];
        m_i[ty * TM + i][tx] = besti[i];
    }
    __syncthreads();
    if (tid < BM) {
        float bv = m_v[tid][0]; int bi = m_i[tid][0];
        #pragma unroll
        for (int t = 1; t < 16; t++) {
            float v = m_v[tid][t]; int ii = m_i[tid][t];
            if (v < bv || (v == bv && ii < bi)) { bv = v; bi = ii; }
        }
        g_idx[row0 + tid] = bi;
    }
}

// ---------------- gather + losses ----------------
__global__ void k_gather(const float* __restrict__ z, float* __restrict__ out) {
    int warp = threadIdx.x >> 5, lane = threadIdx.x & 31;
    int row = blockIdx.x * 8 + warp;
    int k = g_idx[row];
    if (lane == 0) {
        atomicAdd(&g_hist[k], 1);
        out[QSIZE + row] = (float)k;
    }
    const float* er = &g_eT[k * D];
    const float* zr = z + (size_t)row * D;
    float* qr = out + (size_t)row * D;
    float ss = 0.f;
    #pragma unroll
    for (int d = lane; d < D; d += 32) {
        float q = er[d];
        float zv = zr[d];
        float diff = q - zv;
        ss = fmaf(diff, diff, ss);
        qr[d] = __fadd_rn(zv, __fsub_rn(q, zv));
    }
    #pragma unroll
    for (int off = 16; off; off >>= 1)
        ss += __shfl_xor_sync(0xffffffffu, ss, off);
    __shared__ float wsum[8];
    if (lane == 0) wsum[warp] = ss;
    __syncthreads();
    if (threadIdx.x == 0) {
        float t = 0.f;
        for (int w = 0; w < 8; w++) t += wsum[w];
        g_part[blockIdx.x] = t;
    }
}

__global__ void k_final(float* __restrict__ out) {
    __shared__ double sd[256];
    int t = threadIdx.x;
    double s = 0.0;
    for (int i = t; i < 8192; i += 256) s += (double)g_part[i];
    sd[t] = s;
    __syncthreads();
    for (int off = 128; off; off >>= 1) {
        if (t < off) sd[t] += sd[t + off];
        __syncthreads();
    }
    if (t == 0) {
        float vq = (float)(sd[0] / (double)QSIZE);
        out[QSIZE + NROWS + 0] = vq;
        out[QSIZE + NROWS + 1] = 0.25f * vq;
        float ent = 0.f;
        for (int i = 0; i < K; i++) {
            float p = __fmul_rn((float)g_hist[i], 1.0f / 65536.0f);
            ent = __fadd_rn(ent, __fmul_rn(p, logf(__fadd_rn(p, 1e-10f))));
        }
        out[QSIZE + NROWS + 2] = expf(-ent);
    }
}

extern "C" void kernel_launch(void* const* d_in, const int* in_sizes, int n_in,
                              void* d_out, int out_size) {
    const float* z = (const float*)d_in[0];
    const float* e = (const float*)d_in[1];
    float* out = (float*)d_out;

    cudaFuncSetAttribute(k_phaseA, cudaFuncAttributeMaxDynamicSharedMemorySize, SMEM_TOT);
    cudaFuncSetAttribute(k_rescue, cudaFuncAttributeMaxDynamicSharedMemorySize, RS_SMEM);

    k_init<<<4, 256>>>();
    k_en2<<<4, 256>>>(e);
    k_prep<<<dim3(K / 32, D / 32), dim3(32, 8)>>>(e);
    k_zn2<<<NROWS / 32, 256>>>(z);
    k_phaseA<<<NROWS / 128, 256, SMEM_TOT>>>(z);
    k_reduce<<<NROWS / 8, 256>>>();
    k_rescue<<<256, 256, RS_SMEM>>>(z);
    k_check<<<32, 256>>>(z, e);
    k_fallback<<<NROWS / BM, 256>>>(z, e);
    k_gather<<<NROWS / 8, 256>>>(z, out);
    k_final<<<1, 256>>>(out);
}

// round 6
// speedup vs baseline: 1.3754x; 1.3754x over previous
#include <cuda_runtime.h>
#include <math.h>
#include <stdint.h>

#define NROWS 65536
#define D 256
#define K 1024
#define QSIZE (NROWS*D)

// ---------------- scratch ----------------
__device__ __align__(128) float g_eT[K*D];   // e^T [k][d] for gather
__device__ __align__(128) float g_en2[K];
__device__ __align__(128) float g_zn2[NROWS];
__device__ int   g_idx[NROWS];
__device__ float g_part[8192];
__device__ int   g_hist[K];

// ---------------- f32x2 helpers ----------------
__device__ __forceinline__ void fma2(unsigned long long& acc,
                                     unsigned long long a, unsigned long long b) {
    asm("fma.rn.f32x2 %0, %1, %2, %0;" : "+l"(acc) : "l"(a), "l"(b));
}
__device__ __forceinline__ unsigned long long pack2(float x) {
    unsigned long long r;
    asm("mov.b64 %0, {%1, %2};" : "=l"(r) : "f"(x), "f"(x));
    return r;
}
__device__ __forceinline__ void unpack2(float& lo, float& hi, unsigned long long v) {
    asm("mov.b64 {%0, %1}, %2;" : "=f"(lo), "=f"(hi) : "l"(v));
}

// ---------------- small kernels (R1-validated) ----------------
__global__ void k_init() {
    int t = blockIdx.x * blockDim.x + threadIdx.x;
    if (t < K) g_hist[t] = 0;
}

__global__ void k_en2(const float* __restrict__ e) {
    int k = blockIdx.x * blockDim.x + threadIdx.x;
    if (k >= K) return;
    float s = 0.f;
    for (int d = 0; d < D; ++d) {
        float v = e[d * K + k];
        s = __fadd_rn(s, __fmul_rn(v, v));
    }
    g_en2[k] = s;
}

__global__ void k_prep(const float* __restrict__ e) {
    __shared__ float t[32][33];
    int kb = blockIdx.x * 32, db = blockIdx.y * 32;
    int tx = threadIdx.x, ty = threadIdx.y;  // 32 x 8
    #pragma unroll
    for (int i = 0; i < 32; i += 8)
        t[ty + i][tx] = e[(db + ty + i) * K + kb + tx];
    __syncthreads();
    #pragma unroll
    for (int i = 0; i < 32; i += 8)
        g_eT[(kb + ty + i) * D + db + tx] = t[tx][ty + i];
}

__global__ void k_zn2(const float* __restrict__ z) {
    __shared__ float sz[32][257];
    int row0 = blockIdx.x * 32;
    int tid = threadIdx.x;
    #pragma unroll
    for (int i = 0; i < 32; i++) {
        int l = i * 256 + tid;
        int r = l >> 8, d = l & 255;
        sz[r][d] = z[(size_t)(row0 + r) * D + d];
    }
    __syncthreads();
    if (tid < 32) {
        float s = 0.f;
        for (int d = 0; d < D; ++d) {
            float v = sz[tid][d];
            s = __fadd_rn(s, __fmul_rn(v, v));
        }
        g_zn2[row0 + tid] = s;
    }
}

// ---------------- fused fp32 distance GEMM (FFMA2) + argmin ----------------
#define BM 128
#define BN 128
#define BK 16
#define TM 8
#define TN 8
#define BMP 132

__global__ __launch_bounds__(256, 2)
void k_argmin(const float* __restrict__ z, const float* __restrict__ e) {
    __shared__ float s_zT[BK][BMP];
    __shared__ float s_e[BK][BN];
    __shared__ float s_en2[BN];
    __shared__ float m_v[BM][16];
    __shared__ int   m_i[BM][16];

    int tid = threadIdx.x;
    int tx = tid & 15, ty = tid >> 4;
    int row0 = blockIdx.x * BM;

    float bestv[TM];
    int   besti[TM];
    float my_zn2[TM];
    #pragma unroll
    for (int i = 0; i < TM; i++) {
        bestv[i] = INFINITY;
        besti[i] = 0;
        my_zn2[i] = g_zn2[row0 + ty * TM + i];
    }

    for (int kc = 0; kc < K; kc += BN) {
        __syncthreads();
        if (tid < BN) s_en2[tid] = g_en2[kc + tid];

        // packed accumulators: acc2[i][j2] holds columns (2*j2, 2*j2+1)
        unsigned long long acc2[TM][TN / 2];
        #pragma unroll
        for (int i = 0; i < TM; i++)
            #pragma unroll
            for (int j = 0; j < TN / 2; j++) acc2[i][j] = 0ULL;

        for (int dk = 0; dk < D; dk += BK) {
            #pragma unroll
            for (int i = 0; i < 8; i++) {
                int l = i * 256 + tid;
                int r = l >> 4, d = l & 15;
                s_zT[d][r] = z[(size_t)(row0 + r) * D + dk + d];
                int d2 = l >> 7, k2 = l & 127;
                s_e[d2][k2] = e[(dk + d2) * K + kc + k2];
            }
            __syncthreads();
            #pragma unroll
            for (int d = 0; d < BK; d++) {
                float a[TM];
                float4 a0 = *(const float4*)&s_zT[d][ty * TM];
                float4 a1 = *(const float4*)&s_zT[d][ty * TM + 4];
                a[0]=a0.x; a[1]=a0.y; a[2]=a0.z; a[3]=a0.w;
                a[4]=a1.x; a[5]=a1.y; a[6]=a1.z; a[7]=a1.w;
                // b pairs: consecutive floats already form (j, j+1) f32x2 lanes
                union { float4 v; unsigned long long u[2]; } bu0, bu1;
                bu0.v = *(const float4*)&s_e[d][tx * TN];
                bu1.v = *(const float4*)&s_e[d][tx * TN + 4];
                unsigned long long b2[4] = { bu0.u[0], bu0.u[1], bu1.u[0], bu1.u[1] };
                #pragma unroll
                for (int i = 0; i < TM; i++) {
                    unsigned long long a2 = pack2(a[i]);
                    fma2(acc2[i][0], a2, b2[0]);
                    fma2(acc2[i][1], a2, b2[1]);
                    fma2(acc2[i][2], a2, b2[2]);
                    fma2(acc2[i][3], a2, b2[3]);
                }
            }
            __syncthreads();
        }
        // epilogue: d = fl(fl(zn2 + en2) - 2*t), first-index tie-break (R1-identical)
        #pragma unroll
        for (int i = 0; i < TM; i++) {
            #pragma unroll
            for (int j2 = 0; j2 < TN / 2; j2++) {
                float t0, t1;
                unpack2(t0, t1, acc2[i][j2]);
                int j = 2 * j2;
                float dist0 = __fsub_rn(__fadd_rn(my_zn2[i], s_en2[tx * TN + j]),
                                        2.0f * t0);
                float dist1 = __fsub_rn(__fadd_rn(my_zn2[i], s_en2[tx * TN + j + 1]),
                                        2.0f * t1);
                int code = kc + tx * TN + j;
                if (dist0 < bestv[i]) { bestv[i] = dist0; besti[i] = code; }
                if (dist1 < bestv[i]) { bestv[i] = dist1; besti[i] = code + 1; }
            }
        }
    }

    __syncthreads();
    #pragma unroll
    for (int i = 0; i < TM; i++) {
        m_v[ty * TM + i][tx] = bestv[i];
        m_i[ty * TM + i][tx] = besti[i];
    }
    __syncthreads();
    if (tid < BM) {
        float bv = m_v[tid][0];
        int   bi = m_i[tid][0];
        #pragma unroll
        for (int t = 1; t < 16; t++) {
            float v = m_v[tid][t];
            int ii = m_i[tid][t];
            if (v < bv || (v == bv && ii < bi)) { bv = v; bi = ii; }
        }
        g_idx[row0 + tid] = bi;
    }
}

// ---------------- gather + losses ----------------
__global__ void k_gather(const float* __restrict__ z, float* __restrict__ out) {
    int warp = threadIdx.x >> 5, lane = threadIdx.x & 31;
    int row = blockIdx.x * 8 + warp;
    int k = g_idx[row];
    if (lane == 0) {
        atomicAdd(&g_hist[k], 1);
        out[QSIZE + row] = (float)k;
    }
    const float* er = &g_eT[k * D];
    const float* zr = z + (size_t)row * D;
    float* qr = out + (size_t)row * D;
    float ss = 0.f;
    #pragma unroll
    for (int d = lane; d < D; d += 32) {
        float q = er[d];
        float zv = zr[d];
        float diff = q - zv;
        ss = fmaf(diff, diff, ss);
        qr[d] = __fadd_rn(zv, __fsub_rn(q, zv));
    }
    #pragma unroll
    for (int off = 16; off; off >>= 1)
        ss += __shfl_xor_sync(0xffffffffu, ss, off);
    __shared__ float wsum[8];
    if (lane == 0) wsum[warp] = ss;
    __syncthreads();
    if (threadIdx.x == 0) {
        float t = 0.f;
        for (int w = 0; w < 8; w++) t += wsum[w];
        g_part[blockIdx.x] = t;
    }
}

__global__ void k_final(float* __restrict__ out) {
    __shared__ double sd[256];
    int t = threadIdx.x;
    double s = 0.0;
    for (int i = t; i < 8192; i += 256) s += (double)g_part[i];
    sd[t] = s;
    __syncthreads();
    for (int off = 128; off; off >>= 1) {
        if (t < off) sd[t] += sd[t + off];
        __syncthreads();
    }
    if (t == 0) {
        float vq = (float)(sd[0] / (double)QSIZE);
        out[QSIZE + NROWS + 0] = vq;
        out[QSIZE + NROWS + 1] = 0.25f * vq;
        float ent = 0.f;
        for (int i = 0; i < K; i++) {
            float p = __fmul_rn((float)g_hist[i], 1.0f / 65536.0f);
            ent = __fadd_rn(ent, __fmul_rn(p, logf(__fadd_rn(p, 1e-10f))));
        }
        out[QSIZE + NROWS + 2] = expf(-ent);
    }
}

extern "C" void kernel_launch(void* const* d_in, const int* in_sizes, int n_in,
                              void* d_out, int out_size) {
    const float* z = (const float*)d_in[0];
    const float* e = (const float*)d_in[1];
    float* out = (float*)d_out;

    k_init<<<4, 256>>>();
    k_en2<<<4, 256>>>(e);
    k_prep<<<dim3(K / 32, D / 32), dim3(32, 8)>>>(e);
    k_zn2<<<NROWS / 32, 256>>>(z);
    k_argmin<<<NROWS / BM, 256>>>(z, e);
    k_gather<<<NROWS / 8, 256>>>(z, out);
    k_final<<<1, 256>>>(out);
}